// round 2
// baseline (speedup 1.0000x reference)
#include <cuda_runtime.h>

// Shapes (fixed by the problem)
#define BQ 8
#define NQ 16384
#define DQ 768
#define CQ 8
#define NCQ 2

#define BPB 128                    // blocks per batch
#define THREADS 256                // 8 warps per block
#define WARPS_PER_BATCH (BPB * 8)  // 1024
#define ROWS_PER_WARP (NQ / WARPS_PER_BATCH)  // 16

// Scratch: per (batch, cluster) segment: [dot_w0_sum, dot_w1_sum, count]
__device__ float g_accum[BQ * CQ * 3];

__global__ void zero_kernel() {
    int i = threadIdx.x;
    if (i < BQ * CQ * 3) g_accum[i] = 0.0f;
}

__global__ __launch_bounds__(THREADS) void reduce_kernel(
    const float* __restrict__ x,      // [B, N, D]
    const int*   __restrict__ labels, // [B, N]
    const float* __restrict__ w)      // [NC, D]
{
    __shared__ float s_bins[CQ * 3];
    const int tid  = threadIdx.x;
    const int lane = tid & 31;
    const int warp = tid >> 5;

    if (tid < CQ * 3) s_bins[tid] = 0.0f;
    __syncthreads();

    const int b         = blockIdx.x / BPB;
    const int blk_in_b  = blockIdx.x % BPB;
    const int warp_in_b = blk_in_b * 8 + warp;  // 0..1023

    // Cache head_w in registers: lane l owns float4 chunks {l + 32k}, k=0..5
    // (same lane<->index mapping reused for every row's x vector).
    float4 w0[6], w1[6];
    const float4* w0v = reinterpret_cast<const float4*>(w);
    const float4* w1v = reinterpret_cast<const float4*>(w + DQ);
    #pragma unroll
    for (int k = 0; k < 6; k++) {
        w0[k] = w0v[lane + 32 * k];
        w1[k] = w1v[lane + 32 * k];
    }

    const long base = (long)b * NQ;

    for (int r = 0; r < ROWS_PER_WARP; r++) {
        const int row = warp_in_b + r * WARPS_PER_BATCH;
        const float4* xv =
            reinterpret_cast<const float4*>(x + (base + row) * (long)DQ);

        // Load all 6 float4 first (MLP=6), then FMA.
        float4 v[6];
        #pragma unroll
        for (int k = 0; k < 6; k++) v[k] = xv[lane + 32 * k];

        float d0 = 0.0f, d1 = 0.0f;
        #pragma unroll
        for (int k = 0; k < 6; k++) {
            d0 += v[k].x * w0[k].x + v[k].y * w0[k].y
                + v[k].z * w0[k].z + v[k].w * w0[k].w;
            d1 += v[k].x * w1[k].x + v[k].y * w1[k].y
                + v[k].z * w1[k].z + v[k].w * w1[k].w;
        }

        // warp reduce both dots
        #pragma unroll
        for (int off = 16; off > 0; off >>= 1) {
            d0 += __shfl_down_sync(0xffffffffu, d0, off);
            d1 += __shfl_down_sync(0xffffffffu, d1, off);
        }

        if (lane == 0) {
            const int c = labels[base + row];
            atomicAdd(&s_bins[c * 3 + 0], d0);
            atomicAdd(&s_bins[c * 3 + 1], d1);
            atomicAdd(&s_bins[c * 3 + 2], 1.0f);
        }
    }

    __syncthreads();
    if (tid < CQ * 3) atomicAdd(&g_accum[b * CQ * 3 + tid], s_bins[tid]);
}

__global__ void finalize_kernel(const float* __restrict__ hb,
                                float* __restrict__ out)
{
    const int b = threadIdx.x;
    if (b >= BQ) return;

    float best = -3.402823466e+38f;
    float bl0 = 0.0f, bl1 = 0.0f;
    #pragma unroll
    for (int c = 0; c < CQ; c++) {
        const float s0  = g_accum[(b * CQ + c) * 3 + 0];
        const float s1  = g_accum[(b * CQ + c) * 3 + 1];
        const float cnt = g_accum[(b * CQ + c) * 3 + 2];
        const float inv = 1.0f / fmaxf(cnt, 1.0f);
        const float l0 = s0 * inv + hb[0];
        const float l1 = s1 * inv + hb[1];
        // NC=2: 1 - softmax(l)[0] = sigmoid(l1 - l0), monotone in (l1 - l0).
        const float score = l1 - l0;
        if (score > best) { best = score; bl0 = l0; bl1 = l1; }
    }
    out[b * NCQ + 0] = bl0;
    out[b * NCQ + 1] = bl1;
}

extern "C" void kernel_launch(void* const* d_in, const int* in_sizes, int n_in,
                              void* d_out, int out_size)
{
    const float* x      = (const float*)d_in[0]; // inst_feat [8,16384,768] f32
    const int*   labels = (const int*)  d_in[1]; // [8,16384] i32
    const float* w      = (const float*)d_in[2]; // head_w [2,768] f32
    const float* hb     = (const float*)d_in[3]; // head_b [2] f32
    float* out = (float*)d_out;                  // [8,2] f32

    zero_kernel<<<1, 192>>>();
    reduce_kernel<<<BQ * BPB, THREADS>>>(x, labels, w);
    finalize_kernel<<<1, 32>>>(hb, out);
}

// round 5
// speedup vs baseline: 1.0875x; 1.0875x over previous
#include <cuda_runtime.h>
#include <cfloat>

// Shapes (fixed by the problem)
#define BQ 8
#define NQ 16384
#define DQ 768
#define CQ 8
#define NCQ 2

#define THREADS 256
#define WARPS_PER_BLOCK 8
#define BPB 256                                   // blocks per batch
#define GRID (BQ * BPB)                           // 2048
#define WARPS_PER_BATCH (BPB * WARPS_PER_BLOCK)   // 2048
#define ROWS_PER_WARP (NQ / WARPS_PER_BATCH)      // 8

// Scratch per (batch, cluster): [dot_w0_sum, dot_w1_sum, count].
// Zero at module load; the finalizing block re-zeros it each replay.
__device__ float        g_accum[BQ * CQ * 3];
__device__ unsigned int g_ticket;

__global__ __launch_bounds__(THREADS, 2) void fused_kernel(
    const float* __restrict__ x,      // [B, N, D]
    const int*   __restrict__ labels, // [B, N]
    const float* __restrict__ w,      // [NC, D]
    const float* __restrict__ hb,     // [NC]
    float*       __restrict__ out)    // [B, NC]
{
    __shared__ float s_bins[CQ * 3];
    __shared__ int   s_last;

    const int tid  = threadIdx.x;
    const int lane = tid & 31;
    const int warp = tid >> 5;

    if (tid < CQ * 3) s_bins[tid] = 0.0f;
    __syncthreads();

    const int b         = blockIdx.x / BPB;
    const int warp_in_b = (blockIdx.x % BPB) * WARPS_PER_BLOCK + warp;

    // head_w cached in registers: lane l owns float4 chunks {l + 32k}, k=0..5.
    float4 w0[6], w1[6];
    {
        const float4* w0v = reinterpret_cast<const float4*>(w);
        const float4* w1v = reinterpret_cast<const float4*>(w + DQ);
        #pragma unroll
        for (int k = 0; k < 6; k++) {
            w0[k] = w0v[lane + 32 * k];
            w1[k] = w1v[lane + 32 * k];
        }
    }

    // Per-thread, per-cluster accumulators; no cross-lane work in the row loop.
    float acc0[CQ], acc1[CQ], cnt[CQ];
    #pragma unroll
    for (int i = 0; i < CQ; i++) { acc0[i] = 0.0f; acc1[i] = 0.0f; cnt[i] = 0.0f; }

    const long base = (long)b * NQ;

    #pragma unroll 2
    for (int r = 0; r < ROWS_PER_WARP; r++) {
        const int row = warp_in_b + r * WARPS_PER_BATCH;
        const float4* xv =
            reinterpret_cast<const float4*>(x + (base + row) * (long)DQ);

        float4 v[6];
        #pragma unroll
        for (int k = 0; k < 6; k++) v[k] = __ldcs(xv + lane + 32 * k);

        const int c = labels[base + row];   // warp-uniform broadcast load

        float d0 = 0.0f, d1 = 0.0f;
        #pragma unroll
        for (int k = 0; k < 6; k++) {
            d0 = fmaf(v[k].x, w0[k].x, d0); d0 = fmaf(v[k].y, w0[k].y, d0);
            d0 = fmaf(v[k].z, w0[k].z, d0); d0 = fmaf(v[k].w, w0[k].w, d0);
            d1 = fmaf(v[k].x, w1[k].x, d1); d1 = fmaf(v[k].y, w1[k].y, d1);
            d1 = fmaf(v[k].z, w1[k].z, d1); d1 = fmaf(v[k].w, w1[k].w, d1);
        }

        #pragma unroll
        for (int i = 0; i < CQ; i++) {
            if (c == i) {                   // predicated, no divergence (c uniform)
                acc0[i] += d0;
                acc1[i] += d1;
                if (lane == 0) cnt[i] += 1.0f;
            }
        }
    }

    // One warp-reduction per cluster, once per warp (off the row critical path).
    #pragma unroll
    for (int i = 0; i < CQ; i++) {
        #pragma unroll
        for (int off = 16; off > 0; off >>= 1) {
            acc0[i] += __shfl_down_sync(0xffffffffu, acc0[i], off);
            acc1[i] += __shfl_down_sync(0xffffffffu, acc1[i], off);
        }
    }
    if (lane == 0) {
        #pragma unroll
        for (int i = 0; i < CQ; i++) {
            atomicAdd(&s_bins[i * 3 + 0], acc0[i]);
            atomicAdd(&s_bins[i * 3 + 1], acc1[i]);
            atomicAdd(&s_bins[i * 3 + 2], cnt[i]);
        }
    }
    __syncthreads();

    if (tid < CQ * 3) atomicAdd(&g_accum[b * CQ * 3 + tid], s_bins[tid]);
    __threadfence();   // order this block's global atomics before the ticket
    __syncthreads();

    if (tid == 0) {
        unsigned t = atomicAdd(&g_ticket, 1u);
        s_last = (t == (unsigned)(GRID - 1)) ? 1 : 0;
    }
    __syncthreads();
    if (!s_last) return;

    // ---- last block: finalize ----
    __threadfence();
    float bl0 = 0.0f, bl1 = 0.0f;
    const bool isb = (tid < BQ);
    if (isb) {
        const float b0 = hb[0], b1 = hb[1];
        float best = -FLT_MAX;
        #pragma unroll
        for (int c = 0; c < CQ; c++) {
            const float s0 = __ldcg(&g_accum[(tid * CQ + c) * 3 + 0]);
            const float s1 = __ldcg(&g_accum[(tid * CQ + c) * 3 + 1]);
            const float cn = __ldcg(&g_accum[(tid * CQ + c) * 3 + 2]);
            const float inv = 1.0f / fmaxf(cn, 1.0f);
            const float l0 = s0 * inv + b0;
            const float l1 = s1 * inv + b1;
            // NC=2: 1 - softmax(l)[0] = sigmoid(l1 - l0), monotone in (l1 - l0).
            const float score = l1 - l0;
            if (score > best) { best = score; bl0 = l0; bl1 = l1; }
        }
    }
    __syncthreads();   // all reads done before reset
    if (tid < BQ * CQ * 3) g_accum[tid] = 0.0f;   // self-reset for next replay
    if (tid == 0) g_ticket = 0u;
    if (isb) {
        out[tid * NCQ + 0] = bl0;
        out[tid * NCQ + 1] = bl1;
    }
}

extern "C" void kernel_launch(void* const* d_in, const int* in_sizes, int n_in,
                              void* d_out, int out_size)
{
    const float* x      = (const float*)d_in[0]; // inst_feat [8,16384,768] f32
    const int*   labels = (const int*)  d_in[1]; // [8,16384] i32
    const float* w      = (const float*)d_in[2]; // head_w [2,768] f32
    const float* hb     = (const float*)d_in[3]; // head_b [2] f32
    float* out = (float*)d_out;                  // [8,2] f32

    fused_kernel<<<GRID, THREADS>>>(x, labels, w, hb, out);
}

// round 8
// speedup vs baseline: 1.1469x; 1.0546x over previous
#include <cuda_runtime.h>
#include <cfloat>

// Shapes (fixed by the problem)
#define BQ 8
#define NQ 16384
#define DQ 768
#define CQ 8
#define NCQ 2

#define THREADS 256
#define WARPS_PER_BLOCK 8
#define BPB 256                                   // blocks per batch
#define GRID (BQ * BPB)                           // 2048
#define WARPS_PER_BATCH (BPB * WARPS_PER_BLOCK)   // 2048
#define ROWS_PER_WARP (NQ / WARPS_PER_BATCH)      // 8

// Scratch per (batch, cluster): [dot_w0_sum, dot_w1_sum, count].
// Zero at module load; the finalizing block re-zeros it each replay.
__device__ float        g_accum[BQ * CQ * 3];
__device__ unsigned int g_ticket;

__global__ __launch_bounds__(THREADS, 2) void fused_kernel(
    const float* __restrict__ x,      // [B, N, D]
    const int*   __restrict__ labels, // [B, N]
    const float* __restrict__ w,      // [NC, D]
    const float* __restrict__ hb,     // [NC]
    float*       __restrict__ out)    // [B, NC]
{
    __shared__ float4 s_w0[6 * 32];   // head_w row 0, chunk layout [k*32 + lane]
    __shared__ float4 s_w1[6 * 32];   // head_w row 1
    __shared__ float  s_bins[CQ * 3];
    __shared__ int    s_last;

    const int tid  = threadIdx.x;
    const int lane = tid & 31;
    const int warp = tid >> 5;

    if (tid < CQ * 3) s_bins[tid] = 0.0f;
    {   // stage head_w into shared (chunk layout matches per-lane x loads)
        const float4* w0v = reinterpret_cast<const float4*>(w);
        const float4* w1v = reinterpret_cast<const float4*>(w + DQ);
        if (tid < 192) { s_w0[tid] = w0v[tid]; s_w1[tid] = w1v[tid]; }
    }
    __syncthreads();

    const int b         = blockIdx.x / BPB;
    const int warp_in_b = (blockIdx.x % BPB) * WARPS_PER_BLOCK + warp;
    const long base     = (long)b * NQ;

    // Per-thread per-cluster dot accumulators; count lives in ONE register:
    // lane i (i<8) counts rows of cluster i.
    float acc0[CQ], acc1[CQ];
    #pragma unroll
    for (int i = 0; i < CQ; i++) { acc0[i] = 0.0f; acc1[i] = 0.0f; }
    int my_cnt = 0;

    float4 v0[6], v1[6];
    int c0, c1;

    #define LOADROW(buf, cc, r)                                                  \
        do {                                                                     \
            const int  _row = warp_in_b + (r) * WARPS_PER_BATCH;                 \
            const float4* _xv =                                                  \
                reinterpret_cast<const float4*>(x + (base + _row) * (long)DQ);   \
            _Pragma("unroll")                                                    \
            for (int _k = 0; _k < 6; _k++) buf[_k] = __ldcs(_xv + lane + 32*_k); \
            cc = labels[base + _row];                                            \
        } while (0)

    #define COMPUTE(buf, cc)                                                     \
        do {                                                                     \
            float _d0 = 0.0f, _d1 = 0.0f;                                        \
            _Pragma("unroll")                                                    \
            for (int _k = 0; _k < 6; _k++) {                                     \
                const float4 _w0 = s_w0[_k * 32 + lane];                         \
                const float4 _w1 = s_w1[_k * 32 + lane];                         \
                _d0 = fmaf(buf[_k].x, _w0.x, _d0);                               \
                _d0 = fmaf(buf[_k].y, _w0.y, _d0);                               \
                _d0 = fmaf(buf[_k].z, _w0.z, _d0);                               \
                _d0 = fmaf(buf[_k].w, _w0.w, _d0);                               \
                _d1 = fmaf(buf[_k].x, _w1.x, _d1);                               \
                _d1 = fmaf(buf[_k].y, _w1.y, _d1);                               \
                _d1 = fmaf(buf[_k].z, _w1.z, _d1);                               \
                _d1 = fmaf(buf[_k].w, _w1.w, _d1);                               \
            }                                                                    \
            _Pragma("unroll")                                                    \
            for (int _i = 0; _i < CQ; _i++) {                                    \
                if ((cc) == _i) { acc0[_i] += _d0; acc1[_i] += _d1; }            \
            }                                                                    \
            if (lane == (cc)) my_cnt++;                                          \
        } while (0)

    // Software pipeline: loads for row r+1 issue before computing row r.
    LOADROW(v0, c0, 0);
    #pragma unroll
    for (int rr = 0; rr < ROWS_PER_WARP / 2; rr++) {
        LOADROW(v1, c1, 2 * rr + 1);
        COMPUTE(v0, c0);
        if (rr < ROWS_PER_WARP / 2 - 1) LOADROW(v0, c0, 2 * rr + 2);
        COMPUTE(v1, c1);
    }
    #undef LOADROW
    #undef COMPUTE

    // Per-warp tree reduction of the 8 cluster sums (off the critical path).
    #pragma unroll
    for (int i = 0; i < CQ; i++) {
        #pragma unroll
        for (int off = 16; off > 0; off >>= 1) {
            acc0[i] += __shfl_down_sync(0xffffffffu, acc0[i], off);
            acc1[i] += __shfl_down_sync(0xffffffffu, acc1[i], off);
        }
    }
    if (lane == 0) {
        #pragma unroll
        for (int i = 0; i < CQ; i++) {
            atomicAdd(&s_bins[i * 3 + 0], acc0[i]);
            atomicAdd(&s_bins[i * 3 + 1], acc1[i]);
        }
    }
    if (lane < CQ && my_cnt > 0)
        atomicAdd(&s_bins[lane * 3 + 2], (float)my_cnt);
    __syncthreads();

    if (tid < CQ * 3) atomicAdd(&g_accum[b * CQ * 3 + tid], s_bins[tid]);
    __threadfence();   // order this block's global atomics before the ticket
    __syncthreads();

    if (tid == 0) {
        unsigned t = atomicAdd(&g_ticket, 1u);
        s_last = (t == (unsigned)(GRID - 1)) ? 1 : 0;
    }
    __syncthreads();
    if (!s_last) return;

    // ---- last block: finalize ----
    __threadfence();
    float bl0 = 0.0f, bl1 = 0.0f;
    const bool isb = (tid < BQ);
    if (isb) {
        const float b0 = hb[0], b1 = hb[1];
        float best = -FLT_MAX;
        #pragma unroll
        for (int c = 0; c < CQ; c++) {
            const float s0 = __ldcg(&g_accum[(tid * CQ + c) * 3 + 0]);
            const float s1 = __ldcg(&g_accum[(tid * CQ + c) * 3 + 1]);
            const float cn = __ldcg(&g_accum[(tid * CQ + c) * 3 + 2]);
            const float inv = 1.0f / fmaxf(cn, 1.0f);
            const float l0 = s0 * inv + b0;
            const float l1 = s1 * inv + b1;
            // NC=2: 1 - softmax(l)[0] = sigmoid(l1 - l0), monotone in (l1 - l0).
            const float score = l1 - l0;
            if (score > best) { best = score; bl0 = l0; bl1 = l1; }
        }
    }
    __syncthreads();   // all reads of g_accum done before reset
    if (tid < BQ * CQ * 3) g_accum[tid] = 0.0f;   // self-reset for next replay
    if (tid == 0) g_ticket = 0u;
    if (isb) {
        out[tid * NCQ + 0] = bl0;
        out[tid * NCQ + 1] = bl1;
    }
}

extern "C" void kernel_launch(void* const* d_in, const int* in_sizes, int n_in,
                              void* d_out, int out_size)
{
    const float* x      = (const float*)d_in[0]; // inst_feat [8,16384,768] f32
    const int*   labels = (const int*)  d_in[1]; // [8,16384] i32
    const float* w      = (const float*)d_in[2]; // head_w [2,768] f32
    const float* hb     = (const float*)d_in[3]; // head_b [2] f32
    float* out = (float*)d_out;                  // [8,2] f32

    fused_kernel<<<GRID, THREADS>>>(x, labels, w, hb, out);
}